// round 7
// baseline (speedup 1.0000x reference)
#include <cuda_runtime.h>

// Problem constants (fixed by the reference)
#define BATCH 16
#define MCTRL 64          // control points per dim
#define DEG   3           // degree P == Q
#define KLEN  68          // MCTRL + DEG + 1 knots
#define NSPAN 62          // KLEN - 2*DEG candidate spans
#define TPTS  256         // OUT_U == OUT_V
#define IPB   4           // output rows (i values) per block

// Scratch: per-batch basis tables (u==v and V is built from knot_u in the
// reference, so ONE table serves rows and columns).
__device__ float4 g_basis[BATCH * TPTS];  // 4 Cox-de Boor weights
__device__ int    g_win0 [BATCH * TPTS];  // clamped window start (span-3)

// ---------------------------------------------------------------------------
// 32-lane inclusive scan via shfl
// ---------------------------------------------------------------------------
__device__ __forceinline__ float warp_iscan(float v, int lane) {
    #pragma unroll
    for (int off = 1; off < 32; off <<= 1) {
        const float t = __shfl_up_sync(0xffffffffu, v, off);
        if (lane >= off) v += t;
    }
    return v;
}

// ---------------------------------------------------------------------------
// Kernel 1: per-batch basis table. One block per batch, one thread per eval
// point. Warp-0 scan normalizes the knots; each thread does a 6-step binary
// search for its span (argmin of cand[s] = (tp-U[3+s] > 1e-8) ? tp-U[3+s] : 1;
// d strictly decreasing in s -> minimum is the LAST s with d > 1e-8) and the
// Cox-de Boor deg-3 recursion with the reference's exact arithmetic.
// ---------------------------------------------------------------------------
__global__ void __launch_bounds__(TPTS) basis_kernel(
    const float* __restrict__ knot_u)     // [B][68]
{
    __shared__ float U[KLEN];
    const int b = blockIdx.x;
    const int j = threadIdx.x;

    if (j < 32) {
        const float* kb = knot_u + b * KLEN;
        float a0 = kb[j];
        float a1 = kb[j + 32];
        float a2 = (j < KLEN - 64) ? kb[j + 64] : 0.0f;
        const float k0 = __shfl_sync(0xffffffffu, a0, 0);   // knot[0]

        a0 = warp_iscan(a0, j);
        const float tot0 = __shfl_sync(0xffffffffu, a0, 31);
        a1 = warp_iscan(a1, j) + tot0;
        const float tot1 = __shfl_sync(0xffffffffu, a1, 31);
        a2 = warp_iscan(a2, j) + tot1;

        const float last = __shfl_sync(0xffffffffu, a2, KLEN - 64 - 1);
        const float inv  = 1.0f / (last - k0);
        U[j]      = (a0 - k0) * inv;
        U[j + 32] = (a1 - k0) * inv;
        if (j < KLEN - 64) U[j + 64] = (a2 - k0) * inv;
    }
    __syncthreads();

    const float tp = 1e-5f + (float)j * ((1.0f - 2e-5f) / 255.0f);

    int lo = 0, hi = NSPAN - 1;
    #pragma unroll
    for (int it = 0; it < 6; it++) {          // ceil(log2(62)) = 6
        const int mid = (lo + hi + 1) >> 1;
        if (lo < hi) {
            if (tp - U[DEG + mid] > 1e-8f) lo = mid; else hi = mid - 1;
        }
    }
    const int span = lo + DEG;

    float N[DEG + 1];
    N[0] = 1.0f;
    #pragma unroll
    for (int k = 1; k <= DEG; k++) {
        float saved = 0.0f;
        #pragma unroll
        for (int r = 0; r < k; r++) {
            const float K1 = U[span + r + 1];
            const float K2 = U[span + 1 - k + r];
            const float temp = N[r] / ((K1 - tp) + (tp - K2));
            N[r] = saved + (K1 - tp) * temp;
            saved = (tp - K2) * temp;
        }
        N[k] = saved;
    }

    int w0 = span - DEG;
    w0 = w0 < 0 ? 0 : (w0 > MCTRL - 4 ? MCTRL - 4 : w0);

    g_basis[b * TPTS + j] = make_float4(N[0], N[1], N[2], N[3]);
    g_win0 [b * TPTS + j] = w0;
}

// ---------------------------------------------------------------------------
// Kernel 2: surface evaluation, no basis math, ONE barrier.
// Block = (i-tile of IPB rows, batch b), 256 threads (one per j).
// Row weights/windows are uniform across the block -> EVERY thread loads
// them directly from the table (broadcast L2 hits), so there is no
// producer-thread -> smem -> barrier chain at block start. All ~22 front
// LDGs are independent (one L2 round trip for the whole prologue).
//   blend (smem): thread (col,comp): blend[k][col].comp
//                   = sum_l wu[k][l] * ctrl[row0[k]+l][col].comp
//   stencil: per j, per k: out = sum_r wv[r]*blend[k][col0+r] (4 LDS.128).
// ---------------------------------------------------------------------------
__global__ void __launch_bounds__(TPTS) eval_kernel(
    const float4* __restrict__ ctrl,     // [B][64][64] float4
    float*        __restrict__ out)      // [B][256][256][3]
{
    const int b  = blockIdx.y;
    const int i0 = blockIdx.x * IPB;
    const int j  = threadIdx.x;

    __shared__ float4 blend[IPB][MCTRL];      // 4 KB

    // column weights/window for this thread's j (L2 hits)
    const float4 wv   = g_basis[b * TPTS + j];
    const int    col0 = g_win0 [b * TPTS + j];

    // row weights/windows: uniform -> broadcast loads, no smem, no barrier
    float4 wu[IPB];
    int    row0[IPB];
    #pragma unroll
    for (int k = 0; k < IPB; k++) {
        wu[k]   = g_basis[b * TPTS + i0 + k];
        row0[k] = g_win0 [b * TPTS + i0 + k];
    }

    // --- row blends straight from global ---
    // thread j <-> (col = j>>2, comp = j&3); float offset col*4+comp == j,
    // so each row read is a fully-coalesced 128B warp transaction (L2 hit).
    {
        const float* cbase = (const float*)ctrl + (size_t)b * MCTRL * MCTRL * 4;
        #pragma unroll
        for (int k = 0; k < IPB; k++) {
            const float* rp = cbase + (size_t)row0[k] * (MCTRL * 4) + j;
            float acc;
            acc = wu[k].x * rp[0];
            acc = fmaf(wu[k].y, rp[1 * MCTRL * 4], acc);
            acc = fmaf(wu[k].z, rp[2 * MCTRL * 4], acc);
            acc = fmaf(wu[k].w, rp[3 * MCTRL * 4], acc);
            ((float*)blend)[k * MCTRL * 4 + j] = acc;   // blend[k][col].comp
        }
    }
    __syncthreads();    // the only barrier

    // --- column stencil + store (4 LDS.128 per output) ---
    #pragma unroll
    for (int k = 0; k < IPB; k++) {
        const float4 c0 = blend[k][col0 + 0];
        const float4 c1 = blend[k][col0 + 1];
        const float4 c2 = blend[k][col0 + 2];
        const float4 c3 = blend[k][col0 + 3];
        const float x =
            fmaf(wv.x, c0.x, fmaf(wv.y, c1.x, fmaf(wv.z, c2.x, wv.w * c3.x)));
        const float y =
            fmaf(wv.x, c0.y, fmaf(wv.y, c1.y, fmaf(wv.z, c2.y, wv.w * c3.y)));
        const float z =
            fmaf(wv.x, c0.z, fmaf(wv.y, c1.z, fmaf(wv.z, c2.z, wv.w * c3.z)));

        const long long base =
            ((((long long)b * TPTS + (i0 + k)) * TPTS) + j) * 3;
        out[base + 0] = x;
        out[base + 1] = y;
        out[base + 2] = z;
    }
}

// ---------------------------------------------------------------------------
// Launch: tiny basis kernel (16 blocks) then the eval kernel.
// knot_v is unused — the reference builds V from knot_u as well.
// ---------------------------------------------------------------------------
extern "C" void kernel_launch(void* const* d_in, const int* in_sizes, int n_in,
                              void* d_out, int out_size) {
    const float* ctrl   = (const float*)d_in[0];   // [16,64,64,4] f32
    const float* knot_u = (const float*)d_in[1];   // [16,68] f32
    (void)in_sizes; (void)n_in; (void)out_size;

    basis_kernel<<<BATCH, TPTS>>>(knot_u);
    eval_kernel<<<dim3(TPTS / IPB, BATCH), TPTS>>>(
        (const float4*)ctrl, (float*)d_out);
}

// round 9
// speedup vs baseline: 1.1910x; 1.1910x over previous
#include <cuda_runtime.h>

// Problem constants (fixed by the reference)
#define BATCH 16
#define MCTRL 64          // control points per dim
#define DEG   3           // degree P == Q
#define KLEN  68          // MCTRL + DEG + 1 knots
#define NSPAN 62          // KLEN - 2*DEG candidate spans
#define TPTS  256         // OUT_U == OUT_V
#define IPB   8           // output rows (i values) per block

// ---------------------------------------------------------------------------
// Per-thread basis: binary-search span + Cox-de Boor (deg 3), identical
// arithmetic to the reference. U is the normalized knot vector in smem.
// Span = argmin over cand[s] = (tp-U[3+s] > 1e-8) ? tp-U[3+s] : 1.
// U[3..64] strictly increasing -> d strictly decreasing -> minimum is the
// LAST s with d > 1e-8 -> 6-step binary search. s=0 always valid.
// ---------------------------------------------------------------------------
__device__ __forceinline__ void basis_at(const float* __restrict__ U,
                                         float tp, float N[DEG + 1], int& span)
{
    int lo = 0, hi = NSPAN - 1;
    #pragma unroll
    for (int it = 0; it < 6; it++) {           // ceil(log2(62)) = 6
        const int mid = (lo + hi + 1) >> 1;
        if (lo < hi) {
            if (tp - U[DEG + mid] > 1e-8f) lo = mid; else hi = mid - 1;
        }
    }
    span = lo + DEG;

    N[0] = 1.0f;
    #pragma unroll
    for (int k = 1; k <= DEG; k++) {
        float saved = 0.0f;
        #pragma unroll
        for (int r = 0; r < k; r++) {
            const float K1 = U[span + r + 1];
            const float K2 = U[span + 1 - k + r];
            const float temp = N[r] / ((K1 - tp) + (tp - K2));
            N[r] = saved + (K1 - tp) * temp;
            saved = (tp - K2) * temp;
        }
        N[k] = saved;
    }
}

// 32-lane inclusive scan via shfl
__device__ __forceinline__ float warp_iscan(float v, int lane) {
    #pragma unroll
    for (int off = 1; off < 32; off <<= 1) {
        const float t = __shfl_up_sync(0xffffffffu, v, off);
        if (lane >= off) v += t;
    }
    return v;
}

// ---------------------------------------------------------------------------
// Fused kernel. Block = (i-tile of IPB rows, batch b), 256 threads (one per j).
//   0) warp-0 shuffle scan of the 68 knots -> normalized U in smem
//      (Nv==Nu: the reference builds V from knot_u too, and u==v).
//   1) thread j: column basis wv[4]+col0; threads 0..IPB-1: row bases.
//   2) row blend DIRECTLY from global (coalesced LDG.32, L2-resident ctrl):
//      thread (col,comp): blend[k][col].comp = sum_l wu[l]*ctrl[row0+l][col].comp
//   3) per j, per k: out = sum_r wv[r]*blend[k][col0+r]  (4 LDS.128/output).
// The per-thread basis math (~190 inst) is amortized over IPB=8 output rows
// and doubles as latency-hiding work for the L2-dependent blend loads.
// ---------------------------------------------------------------------------
__global__ void __launch_bounds__(TPTS) fused_kernel(
    const float4* __restrict__ ctrl,     // [B][64][64] float4
    const float*  __restrict__ knot_u,   // [B][68]
    float*        __restrict__ out)      // [B][256][256][3]
{
    const int b  = blockIdx.y;
    const int i0 = blockIdx.x * IPB;
    const int j  = threadIdx.x;

    __shared__ float  U[KLEN];
    __shared__ float4 blend[IPB][MCTRL];      // 8 KB
    __shared__ float  wu_s [IPB][4];
    __shared__ int    row0_s[IPB];

    // --- Stage 0: warp-0 scan of knots + normalize ---
    if (j < 32) {
        const float* kb = knot_u + b * KLEN;
        float a0 = kb[j];
        float a1 = kb[j + 32];
        float a2 = (j < KLEN - 64) ? kb[j + 64] : 0.0f;
        const float k0 = __shfl_sync(0xffffffffu, a0, 0);  // knot[0]

        a0 = warp_iscan(a0, j);
        const float tot0 = __shfl_sync(0xffffffffu, a0, 31);
        a1 = warp_iscan(a1, j) + tot0;
        const float tot1 = __shfl_sync(0xffffffffu, a1, 31);
        a2 = warp_iscan(a2, j) + tot1;

        const float last = __shfl_sync(0xffffffffu, a2, KLEN - 64 - 1); // c[67]
        const float inv  = 1.0f / (last - k0);
        U[j]      = (a0 - k0) * inv;
        U[j + 32] = (a1 - k0) * inv;
        if (j < KLEN - 64) U[j + 64] = (a2 - k0) * inv;
    }
    __syncthreads();

    // --- Stage 1: bases ---
    const float step = (1.0f - 2e-5f) / 255.0f;

    float wv[DEG + 1];
    int   spanj;
    basis_at(U, 1e-5f + (float)j * step, wv, spanj);
    int col0 = spanj - DEG;
    col0 = col0 < 0 ? 0 : (col0 > MCTRL - 4 ? MCTRL - 4 : col0);

    if (j < IPB) {
        float wu[DEG + 1];
        int   spani;
        basis_at(U, 1e-5f + (float)(i0 + j) * step, wu, spani);
        int r0 = spani - DEG;
        r0 = r0 < 0 ? 0 : (r0 > MCTRL - 4 ? MCTRL - 4 : r0);
        row0_s[j] = r0;
        #pragma unroll
        for (int l = 0; l <= DEG; l++) wu_s[j][l] = wu[l];
    }
    __syncthreads();

    // --- Stage 2: row blends straight from global ---
    // thread j <-> (col = j>>2, comp = j&3); float offset col*4+comp == j,
    // so each row read is a fully-coalesced 128B warp transaction (L2 hit).
    {
        const float* cbase = (const float*)ctrl + (size_t)b * MCTRL * MCTRL * 4;
        #pragma unroll
        for (int k = 0; k < IPB; k++) {
            const float* rp = cbase + (size_t)row0_s[k] * (MCTRL * 4) + j;
            const float w0 = wu_s[k][0], w1 = wu_s[k][1];
            const float w2 = wu_s[k][2], w3 = wu_s[k][3];
            float acc;
            acc = w0 * rp[0];
            acc = fmaf(w1, rp[1 * MCTRL * 4], acc);
            acc = fmaf(w2, rp[2 * MCTRL * 4], acc);
            acc = fmaf(w3, rp[3 * MCTRL * 4], acc);
            ((float*)blend)[k * MCTRL * 4 + j] = acc;   // blend[k][col].comp
        }
    }
    __syncthreads();

    // --- Stage 3: column stencil + store (4 LDS.128 per output) ---
    #pragma unroll
    for (int k = 0; k < IPB; k++) {
        const float4 c0 = blend[k][col0 + 0];
        const float4 c1 = blend[k][col0 + 1];
        const float4 c2 = blend[k][col0 + 2];
        const float4 c3 = blend[k][col0 + 3];
        const float x =
            fmaf(wv[0], c0.x, fmaf(wv[1], c1.x, fmaf(wv[2], c2.x, wv[3] * c3.x)));
        const float y =
            fmaf(wv[0], c0.y, fmaf(wv[1], c1.y, fmaf(wv[2], c2.y, wv[3] * c3.y)));
        const float z =
            fmaf(wv[0], c0.z, fmaf(wv[1], c1.z, fmaf(wv[2], c2.z, wv[3] * c3.z)));

        const long long base =
            ((((long long)b * TPTS + (i0 + k)) * TPTS) + j) * 3;
        out[base + 0] = x;
        out[base + 1] = y;
        out[base + 2] = z;
    }
}

// ---------------------------------------------------------------------------
// Launch: single fused kernel (knot_v is unused — the reference builds V
// from knot_u as well).
// ---------------------------------------------------------------------------
extern "C" void kernel_launch(void* const* d_in, const int* in_sizes, int n_in,
                              void* d_out, int out_size) {
    const float* ctrl   = (const float*)d_in[0];   // [16,64,64,4] f32
    const float* knot_u = (const float*)d_in[1];   // [16,68] f32
    (void)in_sizes; (void)n_in; (void)out_size;

    fused_kernel<<<dim3(TPTS / IPB, BATCH), TPTS>>>(
        (const float4*)ctrl, knot_u, (float*)d_out);
}